// round 1
// baseline (speedup 1.0000x reference)
#include <cuda_runtime.h>

#define NN 10000
#define NE 160000
#define BB 8
#define DD 64
#define BD 512   // B*D

// -------- device scratch (no runtime allocation allowed) --------
__device__ float g_P[NN * BD];       // state @ W[:64]   (src projection)
__device__ float g_Q[NN * BD];       // state @ W[64:]   (dst projection)
__device__ int   g_cnt[NN];
__device__ int   g_off[NN + 1];
__device__ int   g_cur[NN];
__device__ int   g_esrc[NE];         // CSR-ordered src node per edge
__device__ float g_edist[NE];        // CSR-ordered dist per edge

// ============================================================
// 1) Projection: P = A @ W1, Q = A @ W2;  A = state [80000 x 64]
//    64-row tile per block, 256 threads, 4x4 register micro-tiles.
// ============================================================
__global__ __launch_bounds__(256) void proj_kernel(const float* __restrict__ state,
                                                   const float* __restrict__ weight) {
    __shared__ float sA[DD][68];       // transposed tile, padded row = 272B (16B-aligned)
    __shared__ float sW1[DD][DD];
    __shared__ float sW2[DD][DD];
    int t = threadIdx.x;
    int row0 = blockIdx.x * 64;

    // load both weight halves: weight[k*64+d], k<64 -> src part, k>=64 -> dst part
    for (int i = t; i < DD * DD; i += 256) {
        ((float*)sW1)[i] = weight[i];
        ((float*)sW2)[i] = weight[DD * DD + i];
    }
    // load A tile transposed: sA[k][r]
    {
        int rr = t >> 2;              // 0..63
        int k0 = (t & 3) * 16;        // 0,16,32,48
        #pragma unroll
        for (int j = 0; j < 4; j++) {
            float4 av = *(const float4*)(state + (size_t)(row0 + rr) * DD + k0 + j * 4);
            sA[k0 + j * 4 + 0][rr] = av.x;
            sA[k0 + j * 4 + 1][rr] = av.y;
            sA[k0 + j * 4 + 2][rr] = av.z;
            sA[k0 + j * 4 + 3][rr] = av.w;
        }
    }
    __syncthreads();

    int d0 = (t & 15) * 4;
    int r0 = (t >> 4) * 4;
    float accP[4][4] = {}, accQ[4][4] = {};

    #pragma unroll 8
    for (int k = 0; k < DD; k++) {
        float4 av = *(const float4*)&sA[k][r0];
        float4 w1 = *(const float4*)&sW1[k][d0];
        float4 w2 = *(const float4*)&sW2[k][d0];
        float a_[4]  = {av.x, av.y, av.z, av.w};
        float w1_[4] = {w1.x, w1.y, w1.z, w1.w};
        float w2_[4] = {w2.x, w2.y, w2.z, w2.w};
        #pragma unroll
        for (int i = 0; i < 4; i++)
            #pragma unroll
            for (int j = 0; j < 4; j++) {
                accP[i][j] += a_[i] * w1_[j];
                accQ[i][j] += a_[i] * w2_[j];
            }
    }

    #pragma unroll
    for (int i = 0; i < 4; i++) {
        size_t o = (size_t)(row0 + r0 + i) * DD + d0;
        *(float4*)(g_P + o) = make_float4(accP[i][0], accP[i][1], accP[i][2], accP[i][3]);
        *(float4*)(g_Q + o) = make_float4(accQ[i][0], accQ[i][1], accQ[i][2], accQ[i][3]);
    }
}

// ============================================================
// 2) CSR build by dst
// ============================================================
__global__ void zero_kernel() {
    int i = blockIdx.x * blockDim.x + threadIdx.x;
    if (i < NN) g_cnt[i] = 0;
}

__global__ void hist_kernel(const int* __restrict__ dst) {
    int i = blockIdx.x * blockDim.x + threadIdx.x;
    if (i < NE) atomicAdd(&g_cnt[dst[i]], 1);
}

__global__ void scan_kernel() {
    __shared__ int warp_sums[32];
    __shared__ int s_carry;
    int tid = threadIdx.x;
    int lane = tid & 31, wid = tid >> 5;
    if (tid == 0) s_carry = 0;
    __syncthreads();
    for (int base = 0; base < NN; base += 1024) {
        int idx = base + tid;
        int v = (idx < NN) ? g_cnt[idx] : 0;
        int x = v;
        #pragma unroll
        for (int o = 1; o < 32; o <<= 1) {
            int y = __shfl_up_sync(0xffffffffu, x, o);
            if (lane >= o) x += y;
        }
        if (lane == 31) warp_sums[wid] = x;
        __syncthreads();
        if (wid == 0) {
            int ws = warp_sums[lane];
            #pragma unroll
            for (int o = 1; o < 32; o <<= 1) {
                int y = __shfl_up_sync(0xffffffffu, ws, o);
                if (lane >= o) ws += y;
            }
            warp_sums[lane] = ws;
        }
        __syncthreads();
        int carry = s_carry;
        int excl = carry + (wid ? warp_sums[wid - 1] : 0) + (x - v);
        if (idx < NN) { g_off[idx] = excl; g_cur[idx] = excl; }
        int total = warp_sums[31];
        __syncthreads();
        if (tid == 0) s_carry = carry + total;
        __syncthreads();
    }
    if (threadIdx.x == 0) g_off[NN] = s_carry;
}

__global__ void scatter_kernel(const int* __restrict__ src, const int* __restrict__ dst,
                               const float* __restrict__ dist) {
    int i = blockIdx.x * blockDim.x + threadIdx.x;
    if (i < NE) {
        int d = dst[i];
        int p = atomicAdd(&g_cur[d], 1);
        g_esrc[p]  = src[i];
        g_edist[p] = dist[i];
    }
}

// ============================================================
// 3) Main fused kernel: per dst node, online softmax over incoming edges.
//    Block = node, thread = one (b,d) element (512 = B*D).
// ============================================================
__global__ __launch_bounds__(512) void gat_main(const float* __restrict__ state,
                                                float* __restrict__ out) {
    int n = blockIdx.x;
    int t = threadIdx.x;
    __shared__ int   s_src[512];
    __shared__ float s_dist[512];

    int beg = g_off[n];
    int deg = g_off[n + 1] - beg;
    float q = g_Q[(size_t)n * BD + t];

    float m = -3.402823466e38f;   // running max
    float s = 0.f;                // running sum of exp
    float v = 0.f;                // running weighted numerator

    for (int c0 = 0; c0 < deg; c0 += 512) {
        int cn = min(512, deg - c0);
        __syncthreads();
        if (t < cn) {
            s_src[t]  = g_esrc[beg + c0 + t];
            s_dist[t] = g_edist[beg + c0 + t];
        }
        __syncthreads();
        #pragma unroll 4
        for (int i = 0; i < cn; i++) {
            int   si = s_src[i];
            float de = s_dist[i];
            float p  = __ldg(g_P + (size_t)si * BD + t);
            float x  = __ldg(state + (size_t)si * BD + t);
            float a = p + q;
            a = (a > 0.f) ? a : 0.2f * a;   // leaky_relu(., 0.2)
            a *= de;
            float dlt = a - m;
            if (dlt > 0.f) {                 // new max: rescale running sums
                float c = __expf(-dlt);      // exp(m - a); first iter -> 0
                s = s * c + 1.f;
                v = v * c + x;
                m = a;
            } else {                         // one exp per edge-element
                float w = __expf(dlt);
                s += w;
                v += w * x;
            }
        }
    }

    float r = 0.f;
    if (deg > 0) r = fmaxf(v / s, 0.f);      // relu; empty segment -> 0
    out[(size_t)n * BD + t] = r;
}

// ============================================================
// launcher
// ============================================================
extern "C" void kernel_launch(void* const* d_in, const int* in_sizes, int n_in,
                              void* d_out, int out_size) {
    const float* state  = (const float*)d_in[0];
    // d_in[1] = feature, unused by the math
    const float* weight = (const float*)d_in[2];
    const int*   src    = (const int*)d_in[3];
    const int*   dst    = (const int*)d_in[4];
    const float* dist   = (const float*)d_in[5];
    float* out = (float*)d_out;

    proj_kernel<<<(NN * BB) / 64, 256>>>(state, weight);   // 1250 blocks
    zero_kernel<<<(NN + 255) / 256, 256>>>();
    hist_kernel<<<(NE + 255) / 256, 256>>>(dst);
    scan_kernel<<<1, 1024>>>();
    scatter_kernel<<<(NE + 255) / 256, 256>>>(src, dst, dist);
    gat_main<<<NN, 512>>>(state, out);
}

// round 2
// speedup vs baseline: 1.2853x; 1.2853x over previous
#include <cuda_runtime.h>
#include <cuda_fp16.h>

#define NN 10000
#define NE 160000
#define BB 8
#define DD 64
#define BD 512   // B*D

// -------- device scratch (zero-initialized at module load) --------
__device__ float  g_P[NN * BD];       // state @ W[:64]  (src logit part, fp32)
__device__ float  g_Q[NN * BD];       // state @ W[64:]  (dst logit part, fp32)
__device__ __half g_Xh[NN * BD];      // state values in fp16 (gathered per edge)
__device__ int    g_cnt[NN];          // histogram (reset to 0 by scan each call)
__device__ int    g_off[NN + 1];
__device__ int    g_cur[NN];
__device__ float2 g_edge[NE];         // CSR-ordered (src bits, dist)

// ============================================================
// 1) Projection: P = A @ W1, Q = A @ W2; also emit fp16 copy of A.
//    A = state viewed as [80000 x 64]. 64-row tile, 256 thr, 4x4 microtiles.
// ============================================================
__global__ __launch_bounds__(256) void proj_kernel(const float* __restrict__ state,
                                                   const float* __restrict__ weight) {
    __shared__ float sA[DD][68];
    __shared__ float sW1[DD][DD];
    __shared__ float sW2[DD][DD];
    int t = threadIdx.x;
    int row0 = blockIdx.x * 64;

    for (int i = t; i < DD * DD; i += 256) {
        ((float*)sW1)[i] = weight[i];
        ((float*)sW2)[i] = weight[DD * DD + i];
    }
    {
        int rr = t >> 2;
        int k0 = (t & 3) * 16;
        #pragma unroll
        for (int j = 0; j < 4; j++) {
            float4 av = *(const float4*)(state + (size_t)(row0 + rr) * DD + k0 + j * 4);
            sA[k0 + j * 4 + 0][rr] = av.x;
            sA[k0 + j * 4 + 1][rr] = av.y;
            sA[k0 + j * 4 + 2][rr] = av.z;
            sA[k0 + j * 4 + 3][rr] = av.w;
        }
    }
    __syncthreads();

    int d0 = (t & 15) * 4;
    int r0 = (t >> 4) * 4;
    float accP[4][4] = {}, accQ[4][4] = {};

    #pragma unroll 8
    for (int k = 0; k < DD; k++) {
        float4 av = *(const float4*)&sA[k][r0];
        float4 w1 = *(const float4*)&sW1[k][d0];
        float4 w2 = *(const float4*)&sW2[k][d0];
        float a_[4]  = {av.x, av.y, av.z, av.w};
        float w1_[4] = {w1.x, w1.y, w1.z, w1.w};
        float w2_[4] = {w2.x, w2.y, w2.z, w2.w};
        #pragma unroll
        for (int i = 0; i < 4; i++)
            #pragma unroll
            for (int j = 0; j < 4; j++) {
                accP[i][j] += a_[i] * w1_[j];
                accQ[i][j] += a_[i] * w2_[j];
            }
    }

    #pragma unroll
    for (int i = 0; i < 4; i++) {
        size_t o = (size_t)(row0 + r0 + i) * DD + d0;
        *(float4*)(g_P + o) = make_float4(accP[i][0], accP[i][1], accP[i][2], accP[i][3]);
        *(float4*)(g_Q + o) = make_float4(accQ[i][0], accQ[i][1], accQ[i][2], accQ[i][3]);
        // fp16 copy of the state tile (state[row][d] == sA[d][row-row0])
        __half2 h01 = __floats2half2_rn(sA[d0 + 0][r0 + i], sA[d0 + 1][r0 + i]);
        __half2 h23 = __floats2half2_rn(sA[d0 + 2][r0 + i], sA[d0 + 3][r0 + i]);
        *(__half2*)(g_Xh + o)     = h01;
        *(__half2*)(g_Xh + o + 2) = h23;
    }
}

// ============================================================
// 2) CSR build by dst
// ============================================================
__global__ void hist_kernel(const int* __restrict__ dst) {
    int i = blockIdx.x * blockDim.x + threadIdx.x;
    if (i < NE / 4) {
        int4 d = ((const int4*)dst)[i];
        atomicAdd(&g_cnt[d.x], 1);
        atomicAdd(&g_cnt[d.y], 1);
        atomicAdd(&g_cnt[d.z], 1);
        atomicAdd(&g_cnt[d.w], 1);
    }
}

// Single-block scan: 1024 threads x 10 contiguous elements each.
// Also initializes g_cur and resets g_cnt to 0 for the next call.
__global__ __launch_bounds__(1024) void scan_kernel() {
    __shared__ int warp_sums[32];
    int t = threadIdx.x, lane = t & 31, wid = t >> 5;
    int base = t * 10;
    int pre[10];
    int tsum = 0;
    #pragma unroll
    for (int j = 0; j < 10; j++) {
        int idx = base + j;
        int v = (idx < NN) ? g_cnt[idx] : 0;
        pre[j] = tsum;
        tsum += v;
    }
    int x = tsum;
    #pragma unroll
    for (int o = 1; o < 32; o <<= 1) {
        int y = __shfl_up_sync(0xffffffffu, x, o);
        if (lane >= o) x += y;
    }
    if (lane == 31) warp_sums[wid] = x;
    __syncthreads();
    if (wid == 0) {
        int ws = warp_sums[lane];
        #pragma unroll
        for (int o = 1; o < 32; o <<= 1) {
            int y = __shfl_up_sync(0xffffffffu, ws, o);
            if (lane >= o) ws += y;
        }
        warp_sums[lane] = ws;
    }
    __syncthreads();
    int excl = (wid ? warp_sums[wid - 1] : 0) + (x - tsum);
    #pragma unroll
    for (int j = 0; j < 10; j++) {
        int idx = base + j;
        if (idx < NN) {
            int o = excl + pre[j];
            g_off[idx] = o;
            g_cur[idx] = o;
            g_cnt[idx] = 0;   // reset for next call
        }
    }
    if (t == 0) g_off[NN] = warp_sums[31];
}

__global__ void scatter_kernel(const int* __restrict__ src, const int* __restrict__ dst,
                               const float* __restrict__ dist) {
    int i = blockIdx.x * blockDim.x + threadIdx.x;
    if (i < NE) {
        int d = dst[i];
        int p = atomicAdd(&g_cur[d], 1);
        g_edge[p] = make_float2(__int_as_float(src[i]), dist[i]);
    }
}

// ============================================================
// 3) Main fused kernel: block = dst node, 256 threads x 2 (b,d) elements.
//    Plain (unshifted) softmax — |alpha| <= ~5, exp cannot overflow.
// ============================================================
__global__ __launch_bounds__(256) void gat_main(float* __restrict__ out) {
    int n = blockIdx.x;
    int t = threadIdx.x;

    int beg = g_off[n];
    int end = g_off[n + 1];
    float2 q = *(const float2*)(g_Q + (size_t)n * BD + 2 * t);

    const float2*  Pp = (const float2*)g_P;
    const __half2* Xp = (const __half2*)g_Xh;

    float s0 = 0.f, s1 = 0.f, v0 = 0.f, v1 = 0.f;

    #pragma unroll 4
    for (int e = beg; e < end; e++) {
        float2 ed = __ldg(&g_edge[e]);          // uniform across block, L1-resident
        int   si  = __float_as_int(ed.x);
        float de  = ed.y;
        size_t ro = (size_t)si * 256 + t;
        float2  p  = __ldg(Pp + ro);
        float2  xf = __half22float2(__ldg(Xp + ro));
        float a0 = p.x + q.x; a0 = fmaxf(a0, 0.2f * a0); a0 *= de;
        float a1 = p.y + q.y; a1 = fmaxf(a1, 0.2f * a1); a1 *= de;
        float w0 = __expf(a0);
        float w1 = __expf(a1);
        s0 += w0; v0 = fmaf(w0, xf.x, v0);
        s1 += w1; v1 = fmaf(w1, xf.y, v1);
    }

    float2 r;
    if (end > beg) {
        r.x = fmaxf(v0 / s0, 0.f);
        r.y = fmaxf(v1 / s1, 0.f);
    } else {
        r.x = 0.f; r.y = 0.f;
    }
    *(float2*)(out + (size_t)n * BD + 2 * t) = r;
}

// ============================================================
// launcher
// ============================================================
extern "C" void kernel_launch(void* const* d_in, const int* in_sizes, int n_in,
                              void* d_out, int out_size) {
    const float* state  = (const float*)d_in[0];
    // d_in[1] = feature, unused by the math
    const float* weight = (const float*)d_in[2];
    const int*   src    = (const int*)d_in[3];
    const int*   dst    = (const int*)d_in[4];
    const float* dist   = (const float*)d_in[5];
    float* out = (float*)d_out;

    hist_kernel<<<(NE / 4 + 255) / 256, 256>>>(dst);
    scan_kernel<<<1, 1024>>>();
    scatter_kernel<<<(NE + 255) / 256, 256>>>(src, dst, dist);
    proj_kernel<<<(NN * BB) / 64, 256>>>(state, weight);
    gat_main<<<NN, 256>>>(out);
}

// round 3
// speedup vs baseline: 1.4154x; 1.1013x over previous
#include <cuda_runtime.h>
#include <cuda_fp16.h>
#include <mma.h>

using namespace nvcuda;

#define NN 10000
#define NE 160000
#define BB 8
#define DD 64
#define BD 512   // B*D

// -------- device scratch (zero-initialized at module load) --------
__device__ __half g_Ph[NN * BD];      // state @ W[:64]  (src logit part, fp16)
__device__ float  g_Q[NN * BD];       // state @ W[64:]  (dst logit part, fp32)
__device__ __half g_Xh[NN * BD];      // state values in fp16 (gathered per edge)
__device__ int    g_cnt[NN];          // histogram (reset to 0 by scan each call)
__device__ int    g_off[NN + 1];
__device__ int    g_cur[NN];
__device__ float2 g_edge[NE];         // CSR-ordered (src bits, dist)

// ============================================================
// 1) Projection via tensor cores (HMMA):
//    [P|Q] = A @ Bcat, A = state [80000 x 64] (fp16), Bcat [64 x 128] (fp16).
//    64-row tile per block, 8 warps = 4(M) x 2(N: P-half / Q-half).
//    Also emits the fp16 copy of A (g_Xh) for free.
// ============================================================
__global__ __launch_bounds__(256) void proj_kernel(const float* __restrict__ state,
                                                   const float* __restrict__ weight) {
    __shared__ __half sA[64][72];           // 9216 B  (ldm 72 halves = 144B, 16B-mult)
    __shared__ __half sB[64][128];          // 16384 B
    __shared__ float  sStage[8][16][20];    // 10240 B  (ldm 20 floats = 80B, 16B-mult)
    int t = threadIdx.x;
    int lane = t & 31;
    int row0 = blockIdx.x * 64;

    // Bcat[k][n]: n<64 -> W[k][n] (src half), n>=64 -> W[k+64][n-64] (dst half)
    for (int i = t; i < 64 * 128; i += 256) {
        int k = i >> 7, n = i & 127;
        float w = (n < 64) ? weight[k * 64 + n] : weight[(k + 64) * 64 + (n - 64)];
        sB[k][n] = __float2half(w);
    }
    // A tile (fp16) + coalesced g_Xh write
    {
        int r  = t >> 2;
        int c0 = (t & 3) * 16;
        #pragma unroll
        for (int j = 0; j < 4; j++) {
            float4 v = *(const float4*)(state + (size_t)(row0 + r) * 64 + c0 + j * 4);
            __half2 h01 = __floats2half2_rn(v.x, v.y);
            __half2 h23 = __floats2half2_rn(v.z, v.w);
            *(__half2*)&sA[r][c0 + j * 4]     = h01;
            *(__half2*)&sA[r][c0 + j * 4 + 2] = h23;
            *(__half2*)(g_Xh + (size_t)(row0 + r) * 64 + c0 + j * 4)     = h01;
            *(__half2*)(g_Xh + (size_t)(row0 + r) * 64 + c0 + j * 4 + 2) = h23;
        }
    }
    __syncthreads();

    int wid   = t >> 5;
    int warpM = wid >> 1;          // 0..3
    int warpN = wid & 1;           // 0 = P half, 1 = Q half
    int m0    = warpM * 16;
    int nbase = warpN * 64;

    wmma::fragment<wmma::accumulator, 16, 16, 16, float> acc[4];
    #pragma unroll
    for (int j = 0; j < 4; j++) wmma::fill_fragment(acc[j], 0.f);

    #pragma unroll
    for (int kk = 0; kk < 4; kk++) {
        wmma::fragment<wmma::matrix_a, 16, 16, 16, __half, wmma::row_major> af;
        wmma::load_matrix_sync(af, &sA[m0][kk * 16], 72);
        #pragma unroll
        for (int j = 0; j < 4; j++) {
            wmma::fragment<wmma::matrix_b, 16, 16, 16, __half, wmma::row_major> bf;
            wmma::load_matrix_sync(bf, &sB[kk * 16][nbase + j * 16], 128);
            wmma::mma_sync(acc[j], af, bf, acc[j]);
        }
    }

    if (warpN == 1) {
        // Q: store fp32 directly to global
        #pragma unroll
        for (int j = 0; j < 4; j++)
            wmma::store_matrix_sync(g_Q + (size_t)(row0 + m0) * 64 + j * 16,
                                    acc[j], 64, wmma::mem_row_major);
    } else {
        // P: stage, convert to fp16, write
        #pragma unroll
        for (int j = 0; j < 4; j++) {
            wmma::store_matrix_sync(&sStage[wid][0][0], acc[j], 20, wmma::mem_row_major);
            __syncwarp();
            int lr = lane >> 1;
            int lc = (lane & 1) * 8;
            float4 f0 = *(const float4*)&sStage[wid][lr][lc];
            float4 f1 = *(const float4*)&sStage[wid][lr][lc + 4];
            __half2 h[4];
            h[0] = __floats2half2_rn(f0.x, f0.y);
            h[1] = __floats2half2_rn(f0.z, f0.w);
            h[2] = __floats2half2_rn(f1.x, f1.y);
            h[3] = __floats2half2_rn(f1.z, f1.w);
            *(uint4*)(g_Ph + (size_t)(row0 + m0 + lr) * 64 + j * 16 + lc) = *(uint4*)h;
            __syncwarp();
        }
    }
}

// ============================================================
// 2) CSR build by dst
// ============================================================
__global__ void hist_kernel(const int* __restrict__ dst) {
    int i = blockIdx.x * blockDim.x + threadIdx.x;
    if (i < NE / 4) {
        int4 d = ((const int4*)dst)[i];
        atomicAdd(&g_cnt[d.x], 1);
        atomicAdd(&g_cnt[d.y], 1);
        atomicAdd(&g_cnt[d.z], 1);
        atomicAdd(&g_cnt[d.w], 1);
    }
}

// Single-block scan: 1024 threads x 10 contiguous elements each.
// Initializes g_cur and resets g_cnt to 0 for the next call.
__global__ __launch_bounds__(1024) void scan_kernel() {
    __shared__ int warp_sums[32];
    int t = threadIdx.x, lane = t & 31, wid = t >> 5;
    int base = t * 10;
    int pre[10];
    int tsum = 0;
    #pragma unroll
    for (int j = 0; j < 10; j++) {
        int idx = base + j;
        int v = (idx < NN) ? g_cnt[idx] : 0;
        pre[j] = tsum;
        tsum += v;
    }
    int x = tsum;
    #pragma unroll
    for (int o = 1; o < 32; o <<= 1) {
        int y = __shfl_up_sync(0xffffffffu, x, o);
        if (lane >= o) x += y;
    }
    if (lane == 31) warp_sums[wid] = x;
    __syncthreads();
    if (wid == 0) {
        int ws = warp_sums[lane];
        #pragma unroll
        for (int o = 1; o < 32; o <<= 1) {
            int y = __shfl_up_sync(0xffffffffu, ws, o);
            if (lane >= o) ws += y;
        }
        warp_sums[lane] = ws;
    }
    __syncthreads();
    int excl = (wid ? warp_sums[wid - 1] : 0) + (x - tsum);
    #pragma unroll
    for (int j = 0; j < 10; j++) {
        int idx = base + j;
        if (idx < NN) {
            int o = excl + pre[j];
            g_off[idx] = o;
            g_cur[idx] = o;
            g_cnt[idx] = 0;
        }
    }
    if (t == 0) g_off[NN] = warp_sums[31];
}

__global__ void scatter_kernel(const int* __restrict__ src, const int* __restrict__ dst,
                               const float* __restrict__ dist) {
    int i = blockIdx.x * blockDim.x + threadIdx.x;
    if (i < NE) {
        int d = dst[i];
        int p = atomicAdd(&g_cur[d], 1);
        g_edge[p] = make_float2(__int_as_float(src[i]), dist[i]);
    }
}

// ============================================================
// 3) Main fused kernel: block = dst node, 128 threads x 4 (b,d) elements.
//    Unshifted softmax (|alpha| small, exp cannot overflow).
// ============================================================
__global__ __launch_bounds__(128) void gat_main(float* __restrict__ out) {
    int n = blockIdx.x;
    int t = threadIdx.x;

    int beg = g_off[n];
    int end = g_off[n + 1];
    float4 q = *(const float4*)(g_Q + (size_t)n * BD + 4 * t);

    const uint2* Pp = (const uint2*)g_Ph;   // 4 halves per slot
    const uint2* Xp = (const uint2*)g_Xh;

    float s0 = 0.f, s1 = 0.f, s2 = 0.f, s3 = 0.f;
    float v0 = 0.f, v1 = 0.f, v2 = 0.f, v3 = 0.f;

    #pragma unroll 4
    for (int e = beg; e < end; e++) {
        float2 ed = __ldg(&g_edge[e]);      // uniform across block
        int   si  = __float_as_int(ed.x);
        float de  = ed.y;
        size_t ro = (size_t)si * 128 + t;
        uint2 pu = __ldg(Pp + ro);
        uint2 xu = __ldg(Xp + ro);
        float2 p01 = __half22float2(*(const __half2*)&pu.x);
        float2 p23 = __half22float2(*(const __half2*)&pu.y);
        float2 x01 = __half22float2(*(const __half2*)&xu.x);
        float2 x23 = __half22float2(*(const __half2*)&xu.y);

        float a0 = p01.x + q.x; a0 = fmaxf(a0, 0.2f * a0);
        float a1 = p01.y + q.y; a1 = fmaxf(a1, 0.2f * a1);
        float a2 = p23.x + q.z; a2 = fmaxf(a2, 0.2f * a2);
        float a3 = p23.y + q.w; a3 = fmaxf(a3, 0.2f * a3);

        float w0 = __expf(a0 * de);
        float w1 = __expf(a1 * de);
        float w2 = __expf(a2 * de);
        float w3 = __expf(a3 * de);

        s0 += w0; v0 = fmaf(w0, x01.x, v0);
        s1 += w1; v1 = fmaf(w1, x01.y, v1);
        s2 += w2; v2 = fmaf(w2, x23.x, v2);
        s3 += w3; v3 = fmaf(w3, x23.y, v3);
    }

    float4 r;
    if (end > beg) {
        r.x = fmaxf(v0 / s0, 0.f);
        r.y = fmaxf(v1 / s1, 0.f);
        r.z = fmaxf(v2 / s2, 0.f);
        r.w = fmaxf(v3 / s3, 0.f);
    } else {
        r.x = r.y = r.z = r.w = 0.f;
    }
    *(float4*)(out + (size_t)n * BD + 4 * t) = r;
}

// ============================================================
// launcher
// ============================================================
extern "C" void kernel_launch(void* const* d_in, const int* in_sizes, int n_in,
                              void* d_out, int out_size) {
    const float* state  = (const float*)d_in[0];
    // d_in[1] = feature, unused by the math
    const float* weight = (const float*)d_in[2];
    const int*   src    = (const int*)d_in[3];
    const int*   dst    = (const int*)d_in[4];
    const float* dist   = (const float*)d_in[5];
    float* out = (float*)d_out;

    hist_kernel<<<(NE / 4 + 255) / 256, 256>>>(dst);
    scan_kernel<<<1, 1024>>>();
    scatter_kernel<<<(NE + 255) / 256, 256>>>(src, dst, dist);
    proj_kernel<<<(NN * BB) / 64, 256>>>(state, weight);
    gat_main<<<NN, 128>>>(out);
}

// round 4
// speedup vs baseline: 1.5181x; 1.0726x over previous
#include <cuda_runtime.h>
#include <cuda_fp16.h>
#include <mma.h>

using namespace nvcuda;

#define NN 10000
#define NE 160000
#define BB 8
#define DD 64
#define BD 512   // B*D

// -------- device scratch (zero-initialized at module load) --------
// g_PX[n*128 + t] : .x.y = P halves (dims 4t..4t+3), .z.w = X halves (same dims)
__device__ uint4  g_PX[NN * 128];     // 20 MB
__device__ __half g_Qh[NN * BD];      // 10 MB, dst logit part fp16
__device__ __half g_Bh[64 * 128];     // fp16 [P|Q] weight, k-major rows of 128
__device__ int    g_cnt[NN];          // histogram (reset to 0 by scan each call)
__device__ int    g_off[NN + 1];
__device__ int    g_cur[NN];
__device__ float2 g_edge[NE];         // CSR-ordered (src bits, dist)

// ============================================================
// 0) prep: fp16 weight conversion + dst histogram (fused)
// ============================================================
__global__ void prep_kernel(const float* __restrict__ weight, const int* __restrict__ dst) {
    int i = blockIdx.x * blockDim.x + threadIdx.x;
    if (i < 64 * 128) {
        int k = i >> 7, n = i & 127;
        float w = (n < 64) ? weight[k * 64 + n] : weight[(k + 64) * 64 + (n - 64)];
        g_Bh[i] = __float2half(w);
    }
    if (i < NE / 4) {
        int4 d = ((const int4*)dst)[i];
        atomicAdd(&g_cnt[d.x], 1);
        atomicAdd(&g_cnt[d.y], 1);
        atomicAdd(&g_cnt[d.z], 1);
        atomicAdd(&g_cnt[d.w], 1);
    }
}

// ============================================================
// 1) Projection via tensor cores: [P|Q] = A @ Bcat (fp16 in, fp32 acc).
//    64-row tile per block, 8 warps = 4(M) x 2(N: P half / Q half).
//    Emits X (fp16 state copy) into g_PX for free.
// ============================================================
__global__ __launch_bounds__(256) void proj_kernel(const float* __restrict__ state) {
    __shared__ __half sA[64][72];          // 9216 B
    __shared__ __half sB[64][128];         // 16384 B
    __shared__ float  sStage[8][16][20];   // 10240 B
    int t = threadIdx.x;
    int lane = t & 31, wid = t >> 5;
    int row0 = blockIdx.x * 64;

    // B tile: straight fp16 copy from precomputed g_Bh
    {
        const uint4* sp = (const uint4*)g_Bh;
        uint4* dp = (uint4*)sB;
        #pragma unroll
        for (int j = 0; j < 4; j++) dp[t + 256 * j] = sp[t + 256 * j];
    }
    // A tile fp16 + X write into g_PX (.z,.w)
    #pragma unroll
    for (int pass = 0; pass < 2; pass++) {
        int r = (t >> 3) + pass * 32;      // 0..63
        int g = t & 7;                     // 8-dim group
        const float4* sp = (const float4*)(state + (size_t)(row0 + r) * 64 + g * 8);
        float4 v0 = sp[0], v1 = sp[1];
        __half2 hh[4];
        hh[0] = __floats2half2_rn(v0.x, v0.y);
        hh[1] = __floats2half2_rn(v0.z, v0.w);
        hh[2] = __floats2half2_rn(v1.x, v1.y);
        hh[3] = __floats2half2_rn(v1.z, v1.w);
        *(uint4*)&sA[r][g * 8] = *(uint4*)hh;
        size_t slot = (size_t)(row0 + r) * 16 + 2 * g;   // 16 slots per 64-dim row
        *(uint2*)((char*)&g_PX[slot]     + 8) = *(uint2*)&hh[0];
        *(uint2*)((char*)&g_PX[slot + 1] + 8) = *(uint2*)&hh[2];
    }
    __syncthreads();

    int warpM = wid >> 1;          // 0..3
    int warpN = wid & 1;           // 0 = P half, 1 = Q half
    int m0    = warpM * 16;
    int nbase = warpN * 64;

    wmma::fragment<wmma::accumulator, 16, 16, 16, float> acc[4];
    #pragma unroll
    for (int j = 0; j < 4; j++) wmma::fill_fragment(acc[j], 0.f);

    #pragma unroll
    for (int kk = 0; kk < 4; kk++) {
        wmma::fragment<wmma::matrix_a, 16, 16, 16, __half, wmma::row_major> af;
        wmma::load_matrix_sync(af, &sA[m0][kk * 16], 72);
        #pragma unroll
        for (int j = 0; j < 4; j++) {
            wmma::fragment<wmma::matrix_b, 16, 16, 16, __half, wmma::row_major> bf;
            wmma::load_matrix_sync(bf, &sB[kk * 16][nbase + j * 16], 128);
            wmma::mma_sync(acc[j], af, bf, acc[j]);
        }
    }

    // stage fp32 -> fp16, write P into g_PX (.x,.y) or Q into g_Qh
    #pragma unroll
    for (int j = 0; j < 4; j++) {
        wmma::store_matrix_sync(&sStage[wid][0][0], acc[j], 20, wmma::mem_row_major);
        __syncwarp();
        int lr = lane >> 1;
        int lc = (lane & 1) * 8;
        float4 f0 = *(const float4*)&sStage[wid][lr][lc];
        float4 f1 = *(const float4*)&sStage[wid][lr][lc + 4];
        __half2 h[4];
        h[0] = __floats2half2_rn(f0.x, f0.y);
        h[1] = __floats2half2_rn(f0.z, f0.w);
        h[2] = __floats2half2_rn(f1.x, f1.y);
        h[3] = __floats2half2_rn(f1.z, f1.w);
        int R = row0 + m0 + lr;            // flattened (node*8+b) row
        int d = j * 16 + lc;               // dim 0..63 (multiple of 8)
        if (warpN == 0) {
            size_t s0 = (size_t)R * 16 + (d >> 2);
            *(uint2*)&g_PX[s0]     = *(uint2*)&h[0];
            *(uint2*)&g_PX[s0 + 1] = *(uint2*)&h[2];
        } else {
            *(uint4*)(g_Qh + (size_t)R * 64 + d) = *(uint4*)h;
        }
        __syncwarp();
    }
}

// ============================================================
// 2) CSR build by dst
// ============================================================
// Single-block scan: 1024 threads x 10 contiguous elements each.
// Initializes g_cur and resets g_cnt to 0 for the next call.
__global__ __launch_bounds__(1024) void scan_kernel() {
    __shared__ int warp_sums[32];
    int t = threadIdx.x, lane = t & 31, wid = t >> 5;
    int base = t * 10;
    int pre[10];
    int tsum = 0;
    #pragma unroll
    for (int j = 0; j < 10; j++) {
        int idx = base + j;
        int v = (idx < NN) ? g_cnt[idx] : 0;
        pre[j] = tsum;
        tsum += v;
    }
    int x = tsum;
    #pragma unroll
    for (int o = 1; o < 32; o <<= 1) {
        int y = __shfl_up_sync(0xffffffffu, x, o);
        if (lane >= o) x += y;
    }
    if (lane == 31) warp_sums[wid] = x;
    __syncthreads();
    if (wid == 0) {
        int ws = warp_sums[lane];
        #pragma unroll
        for (int o = 1; o < 32; o <<= 1) {
            int y = __shfl_up_sync(0xffffffffu, ws, o);
            if (lane >= o) ws += y;
        }
        warp_sums[lane] = ws;
    }
    __syncthreads();
    int excl = (wid ? warp_sums[wid - 1] : 0) + (x - tsum);
    #pragma unroll
    for (int j = 0; j < 10; j++) {
        int idx = base + j;
        if (idx < NN) {
            int o = excl + pre[j];
            g_off[idx] = o;
            g_cur[idx] = o;
            g_cnt[idx] = 0;
        }
    }
    if (t == 0) g_off[NN] = warp_sums[31];
}

__global__ void scatter_kernel(const int* __restrict__ src, const int* __restrict__ dst,
                               const float* __restrict__ dist) {
    int i = blockIdx.x * blockDim.x + threadIdx.x;
    if (i < NE) {
        int d = dst[i];
        int p = atomicAdd(&g_cur[d], 1);
        g_edge[p] = make_float2(__int_as_float(src[i]), dist[i]);
    }
}

// ============================================================
// 3) Main fused kernel: block = dst node, 128 threads x 4 (b,d) elements.
//    One uint4 gather per edge per thread (P+X packed).
// ============================================================
__global__ __launch_bounds__(128) void gat_main(float* __restrict__ out) {
    int n = blockIdx.x;
    int t = threadIdx.x;

    int beg = g_off[n];
    int end = g_off[n + 1];

    uint2 qh = *(const uint2*)(g_Qh + (size_t)n * BD + 4 * t);
    float2 q01 = __half22float2(*(const __half2*)&qh.x);
    float2 q23 = __half22float2(*(const __half2*)&qh.y);

    float s0 = 0.f, s1 = 0.f, s2 = 0.f, s3 = 0.f;
    float v0 = 0.f, v1 = 0.f, v2 = 0.f, v3 = 0.f;

    #pragma unroll 4
    for (int e = beg; e < end; e++) {
        float2 ed = __ldg(&g_edge[e]);      // uniform across block
        int   si  = __float_as_int(ed.x);
        float de  = ed.y;
        uint4 px = __ldg(&g_PX[(size_t)si * 128 + t]);
        float2 p01 = __half22float2(*(const __half2*)&px.x);
        float2 p23 = __half22float2(*(const __half2*)&px.y);
        float2 x01 = __half22float2(*(const __half2*)&px.z);
        float2 x23 = __half22float2(*(const __half2*)&px.w);

        float a0 = p01.x + q01.x; a0 = fmaxf(a0, 0.2f * a0);
        float a1 = p01.y + q01.y; a1 = fmaxf(a1, 0.2f * a1);
        float a2 = p23.x + q23.x; a2 = fmaxf(a2, 0.2f * a2);
        float a3 = p23.y + q23.y; a3 = fmaxf(a3, 0.2f * a3);

        float w0 = __expf(a0 * de);
        float w1 = __expf(a1 * de);
        float w2 = __expf(a2 * de);
        float w3 = __expf(a3 * de);

        s0 += w0; v0 = fmaf(w0, x01.x, v0);
        s1 += w1; v1 = fmaf(w1, x01.y, v1);
        s2 += w2; v2 = fmaf(w2, x23.x, v2);
        s3 += w3; v3 = fmaf(w3, x23.y, v3);
    }

    float4 r;
    if (end > beg) {
        r.x = fmaxf(v0 / s0, 0.f);
        r.y = fmaxf(v1 / s1, 0.f);
        r.z = fmaxf(v2 / s2, 0.f);
        r.w = fmaxf(v3 / s3, 0.f);
    } else {
        r.x = r.y = r.z = r.w = 0.f;
    }
    *(float4*)(out + (size_t)n * BD + 4 * t) = r;
}

// ============================================================
// launcher
// ============================================================
extern "C" void kernel_launch(void* const* d_in, const int* in_sizes, int n_in,
                              void* d_out, int out_size) {
    const float* state  = (const float*)d_in[0];
    // d_in[1] = feature, unused by the math
    const float* weight = (const float*)d_in[2];
    const int*   src    = (const int*)d_in[3];
    const int*   dst    = (const int*)d_in[4];
    const float* dist   = (const float*)d_in[5];
    float* out = (float*)d_out;

    prep_kernel<<<(NE / 4 + 255) / 256, 256>>>(weight, dst);
    scan_kernel<<<1, 1024>>>();
    scatter_kernel<<<(NE + 255) / 256, 256>>>(src, dst, dist);
    proj_kernel<<<(NN * BB) / 64, 256>>>(state);
    gat_main<<<NN, 128>>>(out);
}

// round 5
// speedup vs baseline: 1.6156x; 1.0642x over previous
#include <cuda_runtime.h>
#include <cuda_fp16.h>
#include <mma.h>

using namespace nvcuda;

#define NN 10000
#define NE 160000
#define BB 8
#define DD 64
#define BD 512   // B*D

#define PROJ_BLOCKS 1250
#define SCAT_BLOCKS 625   // 625*256 = 160000 = NE

// -------- device scratch (zero-initialized at module load) --------
// g_PX[n*128 + t] : .x.y = P halves (dims 4t..4t+3), .z.w = X halves (same dims)
__device__ uint4  g_PX[NN * 128];     // 20 MB
__device__ __half g_Qh[NN * BD];      // 10 MB, dst logit part fp16
__device__ __half g_Bh[64 * 128];     // fp16 [P|Q] weight, k-major rows of 128
__device__ int    g_cnt[NN];          // histogram (reset to 0 by scan each call)
__device__ int    g_off[NN + 1];
__device__ int    g_cur[NN];
__device__ float2 g_edge[NE];         // CSR-ordered (src bits, dist)

// ============================================================
// 0) prep: fp16 weight conversion + dst histogram (fused)
// ============================================================
__global__ void prep_kernel(const float* __restrict__ weight, const int* __restrict__ dst) {
    int i = blockIdx.x * blockDim.x + threadIdx.x;
    if (i < 64 * 128) {
        int k = i >> 7, n = i & 127;
        float w = (n < 64) ? weight[k * 64 + n] : weight[(k + 64) * 64 + (n - 64)];
        g_Bh[i] = __float2half(w);
    }
    if (i < NE / 4) {
        int4 d = ((const int4*)dst)[i];
        atomicAdd(&g_cnt[d.x], 1);
        atomicAdd(&g_cnt[d.y], 1);
        atomicAdd(&g_cnt[d.z], 1);
        atomicAdd(&g_cnt[d.w], 1);
    }
}

// ============================================================
// 1) Single-block scan: 1024 threads x 10 contiguous elements.
//    Initializes g_cur, resets g_cnt for the next call.
// ============================================================
__global__ __launch_bounds__(1024) void scan_kernel() {
    __shared__ int warp_sums[32];
    int t = threadIdx.x, lane = t & 31, wid = t >> 5;
    int base = t * 10;
    int pre[10];
    int tsum = 0;
    #pragma unroll
    for (int j = 0; j < 10; j++) {
        int idx = base + j;
        int v = (idx < NN) ? g_cnt[idx] : 0;
        pre[j] = tsum;
        tsum += v;
    }
    int x = tsum;
    #pragma unroll
    for (int o = 1; o < 32; o <<= 1) {
        int y = __shfl_up_sync(0xffffffffu, x, o);
        if (lane >= o) x += y;
    }
    if (lane == 31) warp_sums[wid] = x;
    __syncthreads();
    if (wid == 0) {
        int ws = warp_sums[lane];
        #pragma unroll
        for (int o = 1; o < 32; o <<= 1) {
            int y = __shfl_up_sync(0xffffffffu, ws, o);
            if (lane >= o) ws += y;
        }
        warp_sums[lane] = ws;
    }
    __syncthreads();
    int excl = (wid ? warp_sums[wid - 1] : 0) + (x - tsum);
    #pragma unroll
    for (int j = 0; j < 10; j++) {
        int idx = base + j;
        if (idx < NN) {
            int o = excl + pre[j];
            g_off[idx] = o;
            g_cur[idx] = o;
            g_cnt[idx] = 0;
        }
    }
    if (t == 0) g_off[NN] = warp_sums[31];
}

// ============================================================
// 2) Fused: proj (blocks 0..1249) + edge scatter (blocks 1250..1874).
//    proj: [P|Q] = A @ Bcat via HMMA, fp16 accumulators, Q stored
//    straight from the fragment; P staged through a small fp16 buffer.
// ============================================================
__global__ __launch_bounds__(256) void main_kernel(const float* __restrict__ state,
                                                   const int* __restrict__ src,
                                                   const int* __restrict__ dst,
                                                   const float* __restrict__ dist) {
    if (blockIdx.x >= PROJ_BLOCKS) {
        // ---- scatter part ----
        int i = (blockIdx.x - PROJ_BLOCKS) * 256 + threadIdx.x;   // < NE by construction
        int d = dst[i];
        int p = atomicAdd(&g_cur[d], 1);
        g_edge[p] = make_float2(__int_as_float(src[i]), dist[i]);
        return;
    }

    // ---- projection part ----
    __shared__ __half sA[64][72];          // 9216 B
    __shared__ __half sB[64][128];         // 16384 B
    __shared__ __half sP[4][16][24];       // 3072 B, per P-warp fp16 stage
    int t = threadIdx.x;
    int lane = t & 31, wid = t >> 5;
    int row0 = blockIdx.x * 64;

    // B tile: straight fp16 copy from precomputed g_Bh
    {
        const uint4* sp = (const uint4*)g_Bh;
        uint4* dp = (uint4*)sB;
        #pragma unroll
        for (int j = 0; j < 4; j++) dp[t + 256 * j] = sp[t + 256 * j];
    }
    // A tile fp16 + X write into g_PX (.z,.w)
    #pragma unroll
    for (int pass = 0; pass < 2; pass++) {
        int r = (t >> 3) + pass * 32;      // 0..63
        int g = t & 7;                     // 8-dim group
        const float4* sp = (const float4*)(state + (size_t)(row0 + r) * 64 + g * 8);
        float4 v0 = sp[0], v1 = sp[1];
        __half2 hh[4];
        hh[0] = __floats2half2_rn(v0.x, v0.y);
        hh[1] = __floats2half2_rn(v0.z, v0.w);
        hh[2] = __floats2half2_rn(v1.x, v1.y);
        hh[3] = __floats2half2_rn(v1.z, v1.w);
        *(uint4*)&sA[r][g * 8] = *(uint4*)hh;
        size_t slot = (size_t)(row0 + r) * 16 + 2 * g;
        *(uint2*)((char*)&g_PX[slot]     + 8) = *(uint2*)&hh[0];
        *(uint2*)((char*)&g_PX[slot + 1] + 8) = *(uint2*)&hh[2];
    }
    __syncthreads();

    int warpM = wid >> 1;          // 0..3
    int warpN = wid & 1;           // 0 = P half, 1 = Q half
    int m0    = warpM * 16;
    int nbase = warpN * 64;

    wmma::fragment<wmma::accumulator, 16, 16, 16, __half> acc[4];
    #pragma unroll
    for (int j = 0; j < 4; j++) wmma::fill_fragment(acc[j], __float2half(0.f));

    #pragma unroll
    for (int kk = 0; kk < 4; kk++) {
        wmma::fragment<wmma::matrix_a, 16, 16, 16, __half, wmma::row_major> af;
        wmma::load_matrix_sync(af, &sA[m0][kk * 16], 72);
        #pragma unroll
        for (int j = 0; j < 4; j++) {
            wmma::fragment<wmma::matrix_b, 16, 16, 16, __half, wmma::row_major> bf;
            wmma::load_matrix_sync(bf, &sB[kk * 16][nbase + j * 16], 128);
            wmma::mma_sync(acc[j], af, bf, acc[j]);
        }
    }

    if (warpN == 1) {
        // Q: store fp16 fragment straight to global (rows R = row0+m0.., ldm 64)
        #pragma unroll
        for (int j = 0; j < 4; j++)
            wmma::store_matrix_sync(g_Qh + (size_t)(row0 + m0) * 64 + j * 16,
                                    acc[j], 64, wmma::mem_row_major);
    } else {
        // P: fp16 stage -> interleaved g_PX (.x,.y fields)
        int wp = wid >> 1;
        #pragma unroll
        for (int j = 0; j < 4; j++) {
            wmma::store_matrix_sync(&sP[wp][0][0], acc[j], 24, wmma::mem_row_major);
            __syncwarp();
            int lr = lane >> 1;
            int lc = (lane & 1) * 8;
            uint4 hv = *(const uint4*)&sP[wp][lr][lc];   // 8 halves = dims d..d+7
            int R = row0 + m0 + lr;
            int d = j * 16 + lc;
            size_t s0 = (size_t)R * 16 + (d >> 2);
            *(uint2*)&g_PX[s0]     = make_uint2(hv.x, hv.y);
            *(uint2*)&g_PX[s0 + 1] = make_uint2(hv.z, hv.w);
            __syncwarp();
        }
    }
}

// ============================================================
// 3) Main fused kernel: block = dst node, 128 threads x 4 (b,d) elements.
//    2-edge pipelined loop, one uint4 gather per edge per thread.
// ============================================================
__global__ __launch_bounds__(128) void gat_main(float* __restrict__ out) {
    int n = blockIdx.x;
    int t = threadIdx.x;

    int beg = g_off[n];
    int end = g_off[n + 1];

    uint2 qh = *(const uint2*)(g_Qh + (size_t)n * BD + 4 * t);
    float2 q01 = __half22float2(*(const __half2*)&qh.x);
    float2 q23 = __half22float2(*(const __half2*)&qh.y);

    float s0 = 0.f, s1 = 0.f, s2 = 0.f, s3 = 0.f;
    float v0 = 0.f, v1 = 0.f, v2 = 0.f, v3 = 0.f;

    #define GAT_EDGE(SI, DE) do {                                           \
        uint4 px = __ldg(&g_PX[(size_t)(SI) * 128 + t]);                     \
        float2 p01 = __half22float2(*(const __half2*)&px.x);                 \
        float2 p23 = __half22float2(*(const __half2*)&px.y);                 \
        float2 x01 = __half22float2(*(const __half2*)&px.z);                 \
        float2 x23 = __half22float2(*(const __half2*)&px.w);                 \
        float a0 = p01.x + q01.x; a0 = fmaxf(a0, 0.2f * a0);                 \
        float a1 = p01.y + q01.y; a1 = fmaxf(a1, 0.2f * a1);                 \
        float a2 = p23.x + q23.x; a2 = fmaxf(a2, 0.2f * a2);                 \
        float a3 = p23.y + q23.y; a3 = fmaxf(a3, 0.2f * a3);                 \
        float w0 = __expf(a0 * (DE));                                        \
        float w1 = __expf(a1 * (DE));                                        \
        float w2 = __expf(a2 * (DE));                                        \
        float w3 = __expf(a3 * (DE));                                        \
        s0 += w0; v0 = fmaf(w0, x01.x, v0);                                  \
        s1 += w1; v1 = fmaf(w1, x01.y, v1);                                  \
        s2 += w2; v2 = fmaf(w2, x23.x, v2);                                  \
        s3 += w3; v3 = fmaf(w3, x23.y, v3);                                  \
    } while (0)

    int e = beg;
    if ((e & 1) && e < end) {                 // align to float4 boundary
        float2 ed = __ldg(&g_edge[e]);
        GAT_EDGE(__float_as_int(ed.x), ed.y);
        e++;
    }
    for (; e + 1 < end; e += 2) {
        float4 ed = *(const float4*)&g_edge[e];
        int   sA_ = __float_as_int(ed.x);
        int   sB_ = __float_as_int(ed.z);
        uint4 pxa = __ldg(&g_PX[(size_t)sA_ * 128 + t]);
        uint4 pxb = __ldg(&g_PX[(size_t)sB_ * 128 + t]);
        {
            float2 p01 = __half22float2(*(const __half2*)&pxa.x);
            float2 p23 = __half22float2(*(const __half2*)&pxa.y);
            float2 x01 = __half22float2(*(const __half2*)&pxa.z);
            float2 x23 = __half22float2(*(const __half2*)&pxa.w);
            float a0 = p01.x + q01.x; a0 = fmaxf(a0, 0.2f * a0);
            float a1 = p01.y + q01.y; a1 = fmaxf(a1, 0.2f * a1);
            float a2 = p23.x + q23.x; a2 = fmaxf(a2, 0.2f * a2);
            float a3 = p23.y + q23.y; a3 = fmaxf(a3, 0.2f * a3);
            float w0 = __expf(a0 * ed.y);
            float w1 = __expf(a1 * ed.y);
            float w2 = __expf(a2 * ed.y);
            float w3 = __expf(a3 * ed.y);
            s0 += w0; v0 = fmaf(w0, x01.x, v0);
            s1 += w1; v1 = fmaf(w1, x01.y, v1);
            s2 += w2; v2 = fmaf(w2, x23.x, v2);
            s3 += w3; v3 = fmaf(w3, x23.y, v3);
        }
        {
            float2 p01 = __half22float2(*(const __half2*)&pxb.x);
            float2 p23 = __half22float2(*(const __half2*)&pxb.y);
            float2 x01 = __half22float2(*(const __half2*)&pxb.z);
            float2 x23 = __half22float2(*(const __half2*)&pxb.w);
            float a0 = p01.x + q01.x; a0 = fmaxf(a0, 0.2f * a0);
            float a1 = p01.y + q01.y; a1 = fmaxf(a1, 0.2f * a1);
            float a2 = p23.x + q23.x; a2 = fmaxf(a2, 0.2f * a2);
            float a3 = p23.y + q23.y; a3 = fmaxf(a3, 0.2f * a3);
            float w0 = __expf(a0 * ed.w);
            float w1 = __expf(a1 * ed.w);
            float w2 = __expf(a2 * ed.w);
            float w3 = __expf(a3 * ed.w);
            s0 += w0; v0 = fmaf(w0, x01.x, v0);
            s1 += w1; v1 = fmaf(w1, x01.y, v1);
            s2 += w2; v2 = fmaf(w2, x23.x, v2);
            s3 += w3; v3 = fmaf(w3, x23.y, v3);
        }
    }
    if (e < end) {
        float2 ed = __ldg(&g_edge[e]);
        GAT_EDGE(__float_as_int(ed.x), ed.y);
    }
    #undef GAT_EDGE

    float4 r;
    if (end > beg) {
        r.x = fmaxf(v0 / s0, 0.f);
        r.y = fmaxf(v1 / s1, 0.f);
        r.z = fmaxf(v2 / s2, 0.f);
        r.w = fmaxf(v3 / s3, 0.f);
    } else {
        r.x = r.y = r.z = r.w = 0.f;
    }
    *(float4*)(out + (size_t)n * BD + 4 * t) = r;
}

// ============================================================
// launcher
// ============================================================
extern "C" void kernel_launch(void* const* d_in, const int* in_sizes, int n_in,
                              void* d_out, int out_size) {
    const float* state  = (const float*)d_in[0];
    // d_in[1] = feature, unused by the math
    const float* weight = (const float*)d_in[2];
    const int*   src    = (const int*)d_in[3];
    const int*   dst    = (const int*)d_in[4];
    const float* dist   = (const float*)d_in[5];
    float* out = (float*)d_out;

    prep_kernel<<<(NE / 4 + 255) / 256, 256>>>(weight, dst);
    scan_kernel<<<1, 1024>>>();
    main_kernel<<<PROJ_BLOCKS + SCAT_BLOCKS, 256>>>(state, src, dst, dist);
    gat_main<<<NN, 128>>>(out);
}

// round 6
// speedup vs baseline: 1.7059x; 1.0559x over previous
#include <cuda_runtime.h>
#include <cuda_fp16.h>
#include <mma.h>

using namespace nvcuda;

#define NN 10000
#define NE 160000
#define BB 8
#define DD 64
#define BD 512   // B*D

#define PROJ_BLOCKS 1250
#define SCAT_BLOCKS 625   // 625*256 = 160000 = NE

typedef unsigned long long ull;

// -------- device scratch (zero-initialized at module load) --------
__device__ float  g_Pf[NN * BD];      // 20 MB, src logit part fp32
__device__ float  g_Qf[NN * BD];      // 20 MB, dst logit part fp32
__device__ __half g_Bh[64 * 128];     // fp16 [P|Q] weight, k-major rows of 128
__device__ int    g_cnt[NN];          // histogram (reset to 0 by scan each call)
__device__ int    g_off[NN + 1];
__device__ int    g_cur[NN];
__device__ float2 g_edge[NE];         // CSR-ordered (src bits, dist*log2e)

// -------- packed f32x2 helpers (ptxas won't emit these from C++) --------
__device__ __forceinline__ ull pk(float lo, float hi) {
    ull r; asm("mov.b64 %0, {%1,%2};" : "=l"(r) : "f"(lo), "f"(hi)); return r;
}
__device__ __forceinline__ void upk(ull v, float& lo, float& hi) {
    asm("mov.b64 {%0,%1}, %2;" : "=f"(lo), "=f"(hi) : "l"(v));
}
__device__ __forceinline__ ull add2(ull a, ull b) {
    ull r; asm("add.rn.f32x2 %0, %1, %2;" : "=l"(r) : "l"(a), "l"(b)); return r;
}
__device__ __forceinline__ ull mul2(ull a, ull b) {
    ull r; asm("mul.rn.f32x2 %0, %1, %2;" : "=l"(r) : "l"(a), "l"(b)); return r;
}
__device__ __forceinline__ ull fma2(ull a, ull b, ull c) {
    ull r; asm("fma.rn.f32x2 %0, %1, %2, %3;" : "=l"(r) : "l"(a), "l"(b), "l"(c)); return r;
}
__device__ __forceinline__ float ex2f(float x) {
    float r; asm("ex2.approx.ftz.f32 %0, %1;" : "=f"(r) : "f"(x)); return r;
}

// ============================================================
// 0) prep: fp16 weight conversion + dst histogram (fused)
// ============================================================
__global__ void prep_kernel(const float* __restrict__ weight, const int* __restrict__ dst) {
    int i = blockIdx.x * blockDim.x + threadIdx.x;
    if (i < 64 * 128) {
        int k = i >> 7, n = i & 127;
        float w = (n < 64) ? weight[k * 64 + n] : weight[(k + 64) * 64 + (n - 64)];
        g_Bh[i] = __float2half(w);
    }
    if (i < NE / 4) {
        int4 d = ((const int4*)dst)[i];
        atomicAdd(&g_cnt[d.x], 1);
        atomicAdd(&g_cnt[d.y], 1);
        atomicAdd(&g_cnt[d.z], 1);
        atomicAdd(&g_cnt[d.w], 1);
    }
}

// ============================================================
// 1) Single-block scan: 1024 threads x 10 contiguous elements.
// ============================================================
__global__ __launch_bounds__(1024) void scan_kernel() {
    __shared__ int warp_sums[32];
    int t = threadIdx.x, lane = t & 31, wid = t >> 5;
    int base = t * 10;
    int pre[10];
    int tsum = 0;
    #pragma unroll
    for (int j = 0; j < 10; j++) {
        int idx = base + j;
        int v = (idx < NN) ? g_cnt[idx] : 0;
        pre[j] = tsum;
        tsum += v;
    }
    int x = tsum;
    #pragma unroll
    for (int o = 1; o < 32; o <<= 1) {
        int y = __shfl_up_sync(0xffffffffu, x, o);
        if (lane >= o) x += y;
    }
    if (lane == 31) warp_sums[wid] = x;
    __syncthreads();
    if (wid == 0) {
        int ws = warp_sums[lane];
        #pragma unroll
        for (int o = 1; o < 32; o <<= 1) {
            int y = __shfl_up_sync(0xffffffffu, ws, o);
            if (lane >= o) ws += y;
        }
        warp_sums[lane] = ws;
    }
    __syncthreads();
    int excl = (wid ? warp_sums[wid - 1] : 0) + (x - tsum);
    #pragma unroll
    for (int j = 0; j < 10; j++) {
        int idx = base + j;
        if (idx < NN) {
            int o = excl + pre[j];
            g_off[idx] = o;
            g_cur[idx] = o;
            g_cnt[idx] = 0;
        }
    }
    if (t == 0) g_off[NN] = warp_sums[31];
}

// ============================================================
// 2) Fused: proj (blocks 0..1249) + edge scatter (blocks 1250..1874).
//    proj: [P|Q] = A @ Bcat via HMMA (fp16 in, fp32 acc),
//    fragments stored DIRECTLY to fp32 global — no staging, no cvt.
// ============================================================
__global__ __launch_bounds__(256) void main_kernel(const float* __restrict__ state,
                                                   const int* __restrict__ src,
                                                   const int* __restrict__ dst,
                                                   const float* __restrict__ dist) {
    if (blockIdx.x >= PROJ_BLOCKS) {
        // ---- scatter part (dist pre-scaled by log2(e)) ----
        int i = (blockIdx.x - PROJ_BLOCKS) * 256 + threadIdx.x;
        int d = dst[i];
        int p = atomicAdd(&g_cur[d], 1);
        g_edge[p] = make_float2(__int_as_float(src[i]), dist[i] * 1.4426950408889634f);
        return;
    }

    // ---- projection part ----
    __shared__ __half sA[64][72];          // 9216 B
    __shared__ __half sB[64][128];         // 16384 B
    int t = threadIdx.x;
    int wid = t >> 5;
    int row0 = blockIdx.x * 64;

    // B tile: straight fp16 copy from precomputed g_Bh
    {
        const uint4* sp = (const uint4*)g_Bh;
        uint4* dp = (uint4*)sB;
        #pragma unroll
        for (int j = 0; j < 4; j++) dp[t + 256 * j] = sp[t + 256 * j];
    }
    // A tile fp16
    #pragma unroll
    for (int pass = 0; pass < 2; pass++) {
        int r = (t >> 3) + pass * 32;      // 0..63
        int g = t & 7;                     // 8-dim group
        const float4* sp = (const float4*)(state + (size_t)(row0 + r) * 64 + g * 8);
        float4 v0 = sp[0], v1 = sp[1];
        __half2 hh[4];
        hh[0] = __floats2half2_rn(v0.x, v0.y);
        hh[1] = __floats2half2_rn(v0.z, v0.w);
        hh[2] = __floats2half2_rn(v1.x, v1.y);
        hh[3] = __floats2half2_rn(v1.z, v1.w);
        *(uint4*)&sA[r][g * 8] = *(uint4*)hh;
    }
    __syncthreads();

    int warpM = wid >> 1;          // 0..3
    int warpN = wid & 1;           // 0 = P half, 1 = Q half
    int m0    = warpM * 16;
    int nbase = warpN * 64;

    wmma::fragment<wmma::accumulator, 16, 16, 16, float> acc[4];
    #pragma unroll
    for (int j = 0; j < 4; j++) wmma::fill_fragment(acc[j], 0.f);

    #pragma unroll
    for (int kk = 0; kk < 4; kk++) {
        wmma::fragment<wmma::matrix_a, 16, 16, 16, __half, wmma::row_major> af;
        wmma::load_matrix_sync(af, &sA[m0][kk * 16], 72);
        #pragma unroll
        for (int j = 0; j < 4; j++) {
            wmma::fragment<wmma::matrix_b, 16, 16, 16, __half, wmma::row_major> bf;
            wmma::load_matrix_sync(bf, &sB[kk * 16][nbase + j * 16], 128);
            wmma::mma_sync(acc[j], af, bf, acc[j]);
        }
    }

    float* dstP = (warpN == 0) ? g_Pf : g_Qf;
    #pragma unroll
    for (int j = 0; j < 4; j++)
        wmma::store_matrix_sync(dstP + (size_t)(row0 + m0) * 64 + j * 16,
                                acc[j], 64, wmma::mem_row_major);
}

// ============================================================
// 3) Main fused kernel: block = dst node, 128 threads x 4 (b,d) elements.
//    All-fp32, packed f32x2 math, branchless leaky, direct ex2.
// ============================================================
__global__ __launch_bounds__(128) void gat_main(const float* __restrict__ state,
                                                float* __restrict__ out) {
    int n = blockIdx.x;
    int t = threadIdx.x;

    int beg = g_off[n];
    int end = g_off[n + 1];

    const float4* Pp = (const float4*)g_Pf;
    const float4* Xp = (const float4*)state;

    float4 q = __ldg((const float4*)g_Qf + (size_t)n * 128 + t);
    ull q01 = pk(q.x, q.y), q23 = pk(q.z, q.w);
    const ull c06 = pk(0.6f, 0.6f);
    const ull c04 = pk(0.4f, 0.4f);
    const ull AMASK = 0x7FFFFFFF7FFFFFFFULL;

    ull s01 = pk(0.f, 0.f), s23 = s01, v01 = s01, v23 = s01;

    #pragma unroll 4
    for (int e = beg; e < end; e++) {
        float2 ed = __ldg(&g_edge[e]);          // uniform across block
        int   si  = __float_as_int(ed.x);
        ull  de2  = pk(ed.y, ed.y);
        size_t ro = (size_t)si * 128 + t;
        float4 p  = __ldg(Pp + ro);
        float4 x  = __ldg(Xp + ro);

        ull a01 = add2(pk(p.x, p.y), q01);
        ull a23 = add2(pk(p.z, p.w), q23);
        // leaky(a) = 0.6a + 0.4|a|
        ull l01 = fma2(a01, c06, mul2(a01 & AMASK, c04));
        ull l23 = fma2(a23, c06, mul2(a23 & AMASK, c04));
        ull g01 = mul2(l01, de2);
        ull g23 = mul2(l23, de2);

        float f0, f1, f2, f3;
        upk(g01, f0, f1); upk(g23, f2, f3);
        ull w01 = pk(ex2f(f0), ex2f(f1));
        ull w23 = pk(ex2f(f2), ex2f(f3));

        s01 = add2(s01, w01);
        s23 = add2(s23, w23);
        v01 = fma2(w01, pk(x.x, x.y), v01);
        v23 = fma2(w23, pk(x.z, x.w), v23);
    }

    float4 r;
    if (end > beg) {
        float s0, s1, s2, s3, v0, v1, v2, v3;
        upk(s01, s0, s1); upk(s23, s2, s3);
        upk(v01, v0, v1); upk(v23, v2, v3);
        r.x = fmaxf(v0 / s0, 0.f);
        r.y = fmaxf(v1 / s1, 0.f);
        r.z = fmaxf(v2 / s2, 0.f);
        r.w = fmaxf(v3 / s3, 0.f);
    } else {
        r.x = r.y = r.z = r.w = 0.f;
    }
    *(float4*)(out + (size_t)n * BD + 4 * t) = r;
}

// ============================================================
// launcher
// ============================================================
extern "C" void kernel_launch(void* const* d_in, const int* in_sizes, int n_in,
                              void* d_out, int out_size) {
    const float* state  = (const float*)d_in[0];
    // d_in[1] = feature, unused by the math
    const float* weight = (const float*)d_in[2];
    const int*   src    = (const int*)d_in[3];
    const int*   dst    = (const int*)d_in[4];
    const float* dist   = (const float*)d_in[5];
    float* out = (float*)d_out;

    prep_kernel<<<(NE / 4 + 255) / 256, 256>>>(weight, dst);
    scan_kernel<<<1, 1024>>>();
    main_kernel<<<PROJ_BLOCKS + SCAT_BLOCKS, 256>>>(state, src, dst, dist);
    gat_main<<<NN, 128>>>(state, out);
}

// round 7
// speedup vs baseline: 1.8488x; 1.0838x over previous
#include <cuda_runtime.h>
#include <cuda_fp16.h>
#include <mma.h>

using namespace nvcuda;

#define NN 10000
#define NE 160000
#define BB 8
#define DD 64
#define BD 512   // B*D

#define PROJ_BLOCKS 1250
#define SCAT_BLOCKS 625   // 625*256 = 160000 = NE

typedef unsigned long long ull;

// -------- device scratch (zero-initialized at module load) --------
__device__ __half g_Ph[NN * BD];      // 10 MB, src logit part fp16
__device__ __half g_Qh[NN * BD];      // 10 MB, dst logit part fp16
__device__ __half g_Bh[64 * 128];     // fp16 [P|Q] weight, k-major rows of 128
__device__ int    g_cnt[NN];          // histogram (reset to 0 by scan each call)
__device__ int    g_off[NN + 1];
__device__ int    g_cur[NN];
__device__ uint4  g_edge[NE];         // CSR-ordered {src, c1(h2), c2(h2), 0}

// -------- packed f32x2 helpers (ptxas won't emit these from C++) --------
__device__ __forceinline__ ull pk(float lo, float hi) {
    ull r; asm("mov.b64 %0, {%1,%2};" : "=l"(r) : "f"(lo), "f"(hi)); return r;
}
__device__ __forceinline__ void upk(ull v, float& lo, float& hi) {
    asm("mov.b64 {%0,%1}, %2;" : "=f"(lo), "=f"(hi) : "l"(v));
}
__device__ __forceinline__ ull add2(ull a, ull b) {
    ull r; asm("add.rn.f32x2 %0, %1, %2;" : "=l"(r) : "l"(a), "l"(b)); return r;
}
__device__ __forceinline__ ull fma2(ull a, ull b, ull c) {
    ull r; asm("fma.rn.f32x2 %0, %1, %2, %3;" : "=l"(r) : "l"(a), "l"(b), "l"(c)); return r;
}
__device__ __forceinline__ float ex2f(float x) {
    float r; asm("ex2.approx.ftz.f32 %0, %1;" : "=f"(r) : "f"(x)); return r;
}

// ============================================================
// 0) prep: fp16 weight conversion + dst histogram (fused)
// ============================================================
__global__ void prep_kernel(const float* __restrict__ weight, const int* __restrict__ dst) {
    int i = blockIdx.x * blockDim.x + threadIdx.x;
    if (i < 64 * 128) {
        int k = i >> 7, n = i & 127;
        float w = (n < 64) ? weight[k * 64 + n] : weight[(k + 64) * 64 + (n - 64)];
        g_Bh[i] = __float2half(w);
    }
    if (i < NE / 4) {
        int4 d = ((const int4*)dst)[i];
        atomicAdd(&g_cnt[d.x], 1);
        atomicAdd(&g_cnt[d.y], 1);
        atomicAdd(&g_cnt[d.z], 1);
        atomicAdd(&g_cnt[d.w], 1);
    }
}

// ============================================================
// 1) Single-block scan: 1024 threads x 10 contiguous elements.
// ============================================================
__global__ __launch_bounds__(1024) void scan_kernel() {
    __shared__ int warp_sums[32];
    int t = threadIdx.x, lane = t & 31, wid = t >> 5;
    int base = t * 10;
    int pre[10];
    int tsum = 0;
    #pragma unroll
    for (int j = 0; j < 10; j++) {
        int idx = base + j;
        int v = (idx < NN) ? g_cnt[idx] : 0;
        pre[j] = tsum;
        tsum += v;
    }
    int x = tsum;
    #pragma unroll
    for (int o = 1; o < 32; o <<= 1) {
        int y = __shfl_up_sync(0xffffffffu, x, o);
        if (lane >= o) x += y;
    }
    if (lane == 31) warp_sums[wid] = x;
    __syncthreads();
    if (wid == 0) {
        int ws = warp_sums[lane];
        #pragma unroll
        for (int o = 1; o < 32; o <<= 1) {
            int y = __shfl_up_sync(0xffffffffu, ws, o);
            if (lane >= o) ws += y;
        }
        warp_sums[lane] = ws;
    }
    __syncthreads();
    int excl = (wid ? warp_sums[wid - 1] : 0) + (x - tsum);
    #pragma unroll
    for (int j = 0; j < 10; j++) {
        int idx = base + j;
        if (idx < NN) {
            int o = excl + pre[j];
            g_off[idx] = o;
            g_cur[idx] = o;
            g_cnt[idx] = 0;
        }
    }
    if (t == 0) g_off[NN] = warp_sums[31];
}

// ============================================================
// 2) Fused: proj (blocks 0..1249) + edge scatter (blocks 1250..1874).
//    proj: [P|Q] = A @ Bcat via HMMA, fp16 accumulators stored
//    DIRECTLY to fp16 global — no staging, no conversions.
// ============================================================
__global__ __launch_bounds__(256) void main_kernel(const float* __restrict__ state,
                                                   const int* __restrict__ src,
                                                   const int* __restrict__ dst,
                                                   const float* __restrict__ dist) {
    if (blockIdx.x >= PROJ_BLOCKS) {
        // ---- scatter: edge record {src, 0.6*d*log2e (h2), 0.4*d*log2e (h2), 0}
        int i = (blockIdx.x - PROJ_BLOCKS) * 256 + threadIdx.x;
        int d = dst[i];
        int p = atomicAdd(&g_cur[d], 1);
        float f = dist[i] * 1.4426950408889634f;
        __half2 c1 = __float2half2_rn(0.6f * f);
        __half2 c2 = __float2half2_rn(0.4f * f);
        g_edge[p] = make_uint4((unsigned)src[i],
                               *(unsigned*)&c1, *(unsigned*)&c2, 0u);
        return;
    }

    // ---- projection part ----
    __shared__ __half sA[64][72];          // 9216 B
    __shared__ __half sB[64][128];         // 16384 B
    int t = threadIdx.x;
    int wid = t >> 5;
    int row0 = blockIdx.x * 64;

    {
        const uint4* sp = (const uint4*)g_Bh;
        uint4* dp = (uint4*)sB;
        #pragma unroll
        for (int j = 0; j < 4; j++) dp[t + 256 * j] = sp[t + 256 * j];
    }
    #pragma unroll
    for (int pass = 0; pass < 2; pass++) {
        int r = (t >> 3) + pass * 32;
        int g = t & 7;
        const float4* sp = (const float4*)(state + (size_t)(row0 + r) * 64 + g * 8);
        float4 v0 = sp[0], v1 = sp[1];
        __half2 hh[4];
        hh[0] = __floats2half2_rn(v0.x, v0.y);
        hh[1] = __floats2half2_rn(v0.z, v0.w);
        hh[2] = __floats2half2_rn(v1.x, v1.y);
        hh[3] = __floats2half2_rn(v1.z, v1.w);
        *(uint4*)&sA[r][g * 8] = *(uint4*)hh;
    }
    __syncthreads();

    int warpM = wid >> 1;
    int warpN = wid & 1;           // 0 = P half, 1 = Q half
    int m0    = warpM * 16;
    int nbase = warpN * 64;

    wmma::fragment<wmma::accumulator, 16, 16, 16, __half> acc[4];
    #pragma unroll
    for (int j = 0; j < 4; j++) wmma::fill_fragment(acc[j], __float2half(0.f));

    #pragma unroll
    for (int kk = 0; kk < 4; kk++) {
        wmma::fragment<wmma::matrix_a, 16, 16, 16, __half, wmma::row_major> af;
        wmma::load_matrix_sync(af, &sA[m0][kk * 16], 72);
        #pragma unroll
        for (int j = 0; j < 4; j++) {
            wmma::fragment<wmma::matrix_b, 16, 16, 16, __half, wmma::row_major> bf;
            wmma::load_matrix_sync(bf, &sB[kk * 16][nbase + j * 16], 128);
            wmma::mma_sync(acc[j], af, bf, acc[j]);
        }
    }

    __half* dstP = (warpN == 0) ? g_Ph : g_Qh;
    #pragma unroll
    for (int j = 0; j < 4; j++)
        wmma::store_matrix_sync(dstP + (size_t)(row0 + m0) * 64 + j * 16,
                                acc[j], 64, wmma::mem_row_major);
}

// ============================================================
// 3) Main fused kernel: block = dst node, 128 threads x 4 (b,d) elements.
//    fp16 logit path (half2 math), fp32 exp + accumulation, fp32 X gather.
// ============================================================
__global__ __launch_bounds__(128) void gat_main(const float* __restrict__ state,
                                                float* __restrict__ out) {
    int n = blockIdx.x;
    int t = threadIdx.x;

    int beg = g_off[n];
    int end = g_off[n + 1];

    const uint2*  Pp = (const uint2*)g_Ph;     // 4 halves per slot
    const float4* Xp = (const float4*)state;

    uint2 qh = __ldg((const uint2*)g_Qh + (size_t)n * 128 + t);
    __half2 q01 = *(__half2*)&qh.x;
    __half2 q23 = *(__half2*)&qh.y;

    ull s01 = pk(0.f, 0.f), s23 = s01, v01 = s01, v23 = s01;

    #pragma unroll 4
    for (int e = beg; e < end; e++) {
        uint4 ed = __ldg(&g_edge[e]);           // uniform across block
        int si = (int)ed.x;
        __half2 c1 = *(__half2*)&ed.y;
        __half2 c2 = *(__half2*)&ed.z;

        size_t rb = (size_t)si * 128 + t;       // 128 slots per row (both arrays)
        uint2  ph = __ldg(Pp + rb);
        float4 x  = __ldg(Xp + rb);

        __half2 a01 = __hadd2(*(__half2*)&ph.x, q01);
        __half2 a23 = __hadd2(*(__half2*)&ph.y, q23);
        unsigned ab01 = (*(unsigned*)&a01) & 0x7FFF7FFFu;   // |a| per half
        unsigned ab23 = (*(unsigned*)&a23) & 0x7FFF7FFFu;
        // g = a*c1 + |a|*c2  (= leaky(a) * dist * log2e)
        __half2 g01 = __hfma2(a01, c1, __hmul2(*(__half2*)&ab01, c2));
        __half2 g23 = __hfma2(a23, c1, __hmul2(*(__half2*)&ab23, c2));

        float2 f01 = __half22float2(g01);
        float2 f23 = __half22float2(g23);
        ull w01 = pk(ex2f(f01.x), ex2f(f01.y));
        ull w23 = pk(ex2f(f23.x), ex2f(f23.y));

        s01 = add2(s01, w01);
        s23 = add2(s23, w23);
        v01 = fma2(w01, pk(x.x, x.y), v01);
        v23 = fma2(w23, pk(x.z, x.w), v23);
    }

    float4 r;
    if (end > beg) {
        float s0, s1, s2, s3, v0, v1, v2, v3;
        upk(s01, s0, s1); upk(s23, s2, s3);
        upk(v01, v0, v1); upk(v23, v2, v3);
        r.x = fmaxf(v0 / s0, 0.f);
        r.y = fmaxf(v1 / s1, 0.f);
        r.z = fmaxf(v2 / s2, 0.f);
        r.w = fmaxf(v3 / s3, 0.f);
    } else {
        r.x = r.y = r.z = r.w = 0.f;
    }
    *(float4*)(out + (size_t)n * BD + 4 * t) = r;
}

// ============================================================
// launcher
// ============================================================
extern "C" void kernel_launch(void* const* d_in, const int* in_sizes, int n_in,
                              void* d_out, int out_size) {
    const float* state  = (const float*)d_in[0];
    // d_in[1] = feature, unused by the math
    const float* weight = (const float*)d_in[2];
    const int*   src    = (const int*)d_in[3];
    const int*   dst    = (const int*)d_in[4];
    const float* dist   = (const float*)d_in[5];
    float* out = (float*)d_out;

    prep_kernel<<<(NE / 4 + 255) / 256, 256>>>(weight, dst);
    scan_kernel<<<1, 1024>>>();
    main_kernel<<<PROJ_BLOCKS + SCAT_BLOCKS, 256>>>(state, src, dst, dist);
    gat_main<<<NN, 128>>>(state, out);
}